// round 15
// baseline (speedup 1.0000x reference)
#include <cuda_runtime.h>
#include <math.h>

#define BB      8
#define NN1     4096
#define NN2     4096
#define NSLICE  8
#define SLICE   (NN2 / NSLICE)      // 512 pc2 points per slice (8KB float4)
#define GRP     32
#define NGRP    (NN2 / GRP)         // 128 groups per query
#define NGRP_SL (SLICE / GRP)       // 16 groups per slice
#define CUT     30.0f               // exp(s-smax) < e^-30 -> negligible, dropped

// Scratch (device globals — no runtime allocation allowed)
__device__ float g_gmin[BB][NGRP][NN1];   // per-32-group min of d'  (16MB)
__device__ float g_near[BB * 3 * NN1];
__device__ float g_dist[BB * NN1];

// d' = |p2|^2 - 2 q.p2, with EXPLICIT fmaf ordering so pass 1 and pass 2
// produce bitwise-identical values for the same inputs (argmin guarantee).
__device__ __forceinline__ float dp_calc(float qx, float qy, float qz,
                                         float x, float y, float z, float w2)
{
    float dot = fmaf(qx, x, fmaf(qy, y, qz * z));
    return fmaf(-2.0f, dot, w2);
}

// ---------------------------------------------------------------------------
// Kernel 1: per-32-group min of d' over pc2. Branchless scan.
// grid = (NN1/128, NSLICE, BB), 128 threads, 8KB smem -> warp-slot limited.
// ---------------------------------------------------------------------------
__global__ void __launch_bounds__(128) groupmin_kernel(const float* __restrict__ pc1,
                                                       const float* __restrict__ pc2)
{
    __shared__ float4 sh[SLICE];
    const int b = blockIdx.z;
    const int s = blockIdx.y;
    const float* p2 = pc2 + (size_t)b * 4 * NN2;
    const int base = s * SLICE;

    for (int m = threadIdx.x; m < SLICE; m += 128) {
        int g = base + m;
        float x = p2[g], y = p2[NN2 + g], z = p2[2 * NN2 + g];
        float w2 = fmaf(x, x, fmaf(y, y, z * z));
        sh[m] = make_float4(x, y, z, w2);
    }
    __syncthreads();

    const int n = blockIdx.x * 128 + threadIdx.x;
    const float* p1 = pc1 + (size_t)b * 4 * NN1;
    const float qx = p1[n], qy = p1[NN1 + n], qz = p1[2 * NN1 + n];

    #pragma unroll
    for (int grp = 0; grp < NGRP_SL; ++grp) {
        float gm = __int_as_float(0x7f800000);
        #pragma unroll
        for (int j = 0; j < GRP; ++j) {
            float4 p = sh[grp * GRP + j];
            gm = fminf(gm, dp_calc(qx, qy, qz, p.x, p.y, p.z, p.w));
        }
        g_gmin[b][s * NGRP_SL + grp][n] = gm;
    }
}

// ---------------------------------------------------------------------------
// Kernel 2: resolve. One thread per query (warp = 32 consecutive queries).
// Phase a: global min over the 128 group-mins -> smax + clamped threshold.
// Phase b: for each group g (SAME pc2 data for every query): ballot the
// lanes whose group-min passes their threshold; if any, cooperatively load
// the 32 points (one per lane) and, for each flagged source lane, broadcast
// its query, compute one weight per lane, butterfly-reduce {w, wx, wy, wz}
// back to the owner. Warp-uniform control flow, no atomics, deterministic.
// The argmin element recomputes bitwise-identically (dp_calc) and the
// threshold is clamped to the stored min -> it always passes, sumw >= 1.
// ---------------------------------------------------------------------------
__global__ void __launch_bounds__(128) resolve_kernel(const float* __restrict__ pc1,
                                                      const float* __restrict__ pc2)
{
    const int b = blockIdx.y;
    const int n = blockIdx.x * 128 + threadIdx.x;
    const int lane = threadIdx.x & 31;
    const float* p1 = pc1 + (size_t)b * 4 * NN1;
    const float* p2 = pc2 + (size_t)b * 4 * NN2;

    const float qx = p1[n], qy = p1[NN1 + n], qz = p1[2 * NN1 + n];
    const float q2 = fmaf(qx, qx, fmaf(qy, qy, qz * qz));
    const float INF = __int_as_float(0x7f800000);

    // ---- phase a: global min of d' ----
    float dminp = INF;
    #pragma unroll 8
    for (int g = 0; g < NGRP; ++g)
        dminp = fminf(dminp, g_gmin[b][g][n]);

    const float dmin = dminp + q2;
    const float smax = __fdividef(2.0f, fmaxf(dmin, 1e-5f));
    const float thr = (smax > CUT)
                    ? fmaxf(__fdividef(2.0f, smax - CUT) - q2, dminp)
                    : INF;

    // ---- phase b: gather candidate groups ----
    float sumw = 0.0f, a0 = 0.0f, a1 = 0.0f, a2 = 0.0f;

    for (int g = 0; g < NGRP; ++g) {
        float v = g_gmin[b][g][n];
        unsigned mask = __ballot_sync(0xffffffffu, v <= thr);
        if (mask) {
            const int m = g * GRP + lane;
            const float x = p2[m], y = p2[NN2 + m], z = p2[2 * NN2 + m];
            const float w2 = fmaf(x, x, fmaf(y, y, z * z));
            while (mask) {
                const int src = __ffs(mask) - 1;
                mask &= mask - 1;
                const float sqx = __shfl_sync(0xffffffffu, qx, src);
                const float sqy = __shfl_sync(0xffffffffu, qy, src);
                const float sqz = __shfl_sync(0xffffffffu, qz, src);
                const float sq2 = __shfl_sync(0xffffffffu, q2, src);
                const float ssm = __shfl_sync(0xffffffffu, smax, src);
                const float sth = __shfl_sync(0xffffffffu, thr, src);

                const float dpv = dp_calc(sqx, sqy, sqz, x, y, z, w2);
                float wgt = 0.0f;
                if (dpv <= sth) {
                    float d = fmaxf(dpv + sq2, 1e-5f);
                    float sc = __fdividef(2.0f, d);
                    wgt = __expf(sc - ssm);          // argmin: exp(0) = 1
                }
                float wx = wgt * x, wy = wgt * y, wz = wgt * z;
                #pragma unroll
                for (int o = 16; o > 0; o >>= 1) {
                    wgt += __shfl_xor_sync(0xffffffffu, wgt, o);
                    wx  += __shfl_xor_sync(0xffffffffu, wx, o);
                    wy  += __shfl_xor_sync(0xffffffffu, wy, o);
                    wz  += __shfl_xor_sync(0xffffffffu, wz, o);
                }
                if (lane == src) {
                    sumw += wgt; a0 += wx; a1 += wy; a2 += wz;
                }
            }
        }
    }

    float inv = __fdividef(1.0f, sumw);              // sumw >= 1 (argmin)
    float nx = a0 * inv, ny = a1 * inv, nz = a2 * inv;
    float ddx = qx - nx, ddy = qy - ny, ddz = qz - nz;
    // channel 3: pc1[3]=1, sum(softmax)=1; contribution ~ulp^2 -> omitted
    float dist = sqrtf(ddx * ddx + ddy * ddy + ddz * ddz);

    g_near[((size_t)b * 3 + 0) * NN1 + n] = nx;
    g_near[((size_t)b * 3 + 1) * NN1 + n] = ny;
    g_near[((size_t)b * 3 + 2) * NN1 + n] = nz;
    g_dist[(size_t)b * NN1 + n] = dist;
}

// ---------------------------------------------------------------------------
// Kernel 3: one block per batch. fp32 reductions (mean, masked sums, H),
// thread 0 does the dense tail (SVD/Kabsch/quat) in fp32.
// Output layout: T[8*16] | q[8*4] | t[8*3]
// ---------------------------------------------------------------------------
__device__ inline float det3f(const float A[3][3])
{
    return A[0][0] * (A[1][1] * A[2][2] - A[1][2] * A[2][1])
         - A[0][1] * (A[1][0] * A[2][2] - A[1][2] * A[2][0])
         + A[0][2] * (A[1][0] * A[2][1] - A[1][1] * A[2][0]);
}

__global__ void __launch_bounds__(256) finalize_kernel(const float* __restrict__ pc1,
                                                       float* __restrict__ out)
{
    const int b = blockIdx.x;
    const int tid = threadIdx.x;
    const float* p1 = pc1 + (size_t)b * 4 * NN1;
    const float* nr = g_near + (size_t)b * 3 * NN1;
    const float* ds = g_dist + (size_t)b * NN1;

    __shared__ float warp_red[16][8];
    __shared__ float s_mean;

    // ---- phase 1: mean distance ----
    float lsum = 0.0f;
    for (int i = tid; i < NN1; i += 256) lsum += ds[i];
    for (int o = 16; o > 0; o >>= 1) lsum += __shfl_down_sync(0xffffffffu, lsum, o);
    if ((tid & 31) == 0) warp_red[0][tid >> 5] = lsum;
    __syncthreads();
    if (tid == 0) {
        float t = 0.0f;
        for (int w = 0; w < 8; ++w) t += warp_red[0][w];
        s_mean = t / (float)NN1;
    }
    __syncthreads();
    const float mean = s_mean;

    // ---- phase 2: masked sums (fp32) ----
    float acc[16];
    #pragma unroll
    for (int k = 0; k < 16; ++k) acc[k] = 0.0f;

    for (int i = tid; i < NN1; i += 256) {
        float d = ds[i];
        float z = (d - mean - 1e-5f) * -1e10f;         // REJECT_RATIO=1
        float ind = 1.0f / (1.0f + __expf(-z));        // exact 0/1 step in fp32
        if (ind > 0.0f) {
            float w = ind;
            float x1 = p1[i], y1 = p1[NN1 + i], z1 = p1[2 * NN1 + i];
            float x2 = nr[i], y2 = nr[NN1 + i], z2 = nr[2 * NN1 + i];
            acc[0] += w;
            acc[1] += w * x1;  acc[2] += w * y1;  acc[3] += w * z1;
            acc[4] += w * x2;  acc[5] += w * y2;  acc[6] += w * z2;
            acc[7]  += w * x1 * x2;  acc[8]  += w * x1 * y2;  acc[9]  += w * x1 * z2;
            acc[10] += w * y1 * x2;  acc[11] += w * y1 * y2;  acc[12] += w * y1 * z2;
            acc[13] += w * z1 * x2;  acc[14] += w * z1 * y2;  acc[15] += w * z1 * z2;
        }
    }
    #pragma unroll
    for (int k = 0; k < 16; ++k) {
        float v = acc[k];
        for (int o = 16; o > 0; o >>= 1) v += __shfl_down_sync(0xffffffffu, v, o);
        if ((tid & 31) == 0) warp_red[k][tid >> 5] = v;
    }
    __syncthreads();
    if (tid != 0) return;

    float tot[16];
    for (int k = 0; k < 16; ++k) {
        float t = 0.0f;
        for (int w = 0; w < 8; ++w) t += warp_red[k][w];
        tot[k] = t;
    }

    const float wsum = tot[0];
    const float winv = 1.0f / wsum;
    float c1[3], c2[3], H[3][3];
    for (int i = 0; i < 3; ++i) {
        c1[i] = tot[1 + i] * winv;
        c2[i] = tot[4 + i] * winv;
    }
    for (int i = 0; i < 3; ++i)
        for (int j = 0; j < 3; ++j)
            H[i][j] = tot[7 + i * 3 + j] - tot[1 + i] * tot[4 + j] * winv;

    // ---- fp32 SVD of H via Jacobi on S = H^T H ----
    float S[3][3], V[3][3];
    for (int i = 0; i < 3; ++i)
        for (int j = 0; j < 3; ++j) {
            float t = 0.0f;
            for (int k = 0; k < 3; ++k) t += H[k][i] * H[k][j];
            S[i][j] = t;
            V[i][j] = (i == j) ? 1.0f : 0.0f;
        }
    for (int sweep = 0; sweep < 8; ++sweep) {
        for (int pi = 0; pi < 3; ++pi) {
            const int p = (pi == 2) ? 1 : 0;
            const int q = (pi == 0) ? 1 : 2;
            float apq = S[p][q];
            if (fabsf(apq) < 1e-30f) continue;
            float theta = (S[q][q] - S[p][p]) / (2.0f * apq);
            float tt = copysignf(1.0f, theta) / (fabsf(theta) + sqrtf(theta * theta + 1.0f));
            float c = rsqrtf(tt * tt + 1.0f);
            float sn = tt * c;
            for (int k = 0; k < 3; ++k) { float a = S[k][p], bb = S[k][q]; S[k][p] = c * a - sn * bb; S[k][q] = sn * a + c * bb; }
            for (int k = 0; k < 3; ++k) { float a = S[p][k], bb = S[q][k]; S[p][k] = c * a - sn * bb; S[q][k] = sn * a + c * bb; }
            for (int k = 0; k < 3; ++k) { float a = V[k][p], bb = V[k][q]; V[k][p] = c * a - sn * bb; V[k][q] = sn * a + c * bb; }
        }
    }
    float lam[3] = { S[0][0], S[1][1], S[2][2] };
    for (int i = 0; i < 2; ++i)
        for (int j = i + 1; j < 3; ++j)
            if (lam[j] > lam[i]) {
                float t = lam[i]; lam[i] = lam[j]; lam[j] = t;
                for (int k = 0; k < 3; ++k) { float v = V[k][i]; V[k][i] = V[k][j]; V[k][j] = v; }
            }

    // U columns: u_i = H v_i, Gram-Schmidt orthonormalized (keeps det sign)
    float U[3][3];
    for (int i = 0; i < 3; ++i) {
        float u[3];
        for (int k = 0; k < 3; ++k) {
            float t = 0.0f;
            for (int j = 0; j < 3; ++j) t += H[k][j] * V[j][i];
            u[k] = t;
        }
        for (int pc = 0; pc < i; ++pc) {
            float dpp = u[0] * U[0][pc] + u[1] * U[1][pc] + u[2] * U[2][pc];
            for (int k = 0; k < 3; ++k) u[k] -= dpp * U[k][pc];
        }
        float nrm = sqrtf(u[0] * u[0] + u[1] * u[1] + u[2] * u[2]);
        float innr = 1.0f / fmaxf(nrm, 1e-30f);
        for (int k = 0; k < 3; ++k) U[k][i] = u[k] * innr;
    }

    float sign = (det3f(U) * det3f(V) < 0.0f) ? -1.0f : 1.0f;
    for (int k = 0; k < 3; ++k) V[k][2] *= sign;

    float R[3][3];
    for (int i = 0; i < 3; ++i)
        for (int j = 0; j < 3; ++j) {
            float t = 0.0f;
            for (int k = 0; k < 3; ++k) t += V[i][k] * U[j][k];
            R[i][j] = t;
        }
    float tv[3];
    for (int i = 0; i < 3; ++i)
        tv[i] = c2[i] - (R[i][0] * c1[0] + R[i][1] * c1[1] + R[i][2] * c1[2]);

    // ---- write outputs: T | q | t ----
    float* To = out + b * 16;
    for (int i = 0; i < 3; ++i) {
        for (int j = 0; j < 3; ++j) To[i * 4 + j] = R[i][j];
        To[i * 4 + 3] = tv[i];
    }
    To[12] = 0.0f; To[13] = 0.0f; To[14] = 0.0f; To[15] = 1.0f;

    float trp = R[0][0] + R[1][1] + R[2][2];
    float qw = 0.5f * sqrtf(fmaxf(1.0f + trp, 1e-12f));
    float qxv = 0.5f * sqrtf(fmaxf(1.0f + R[0][0] - R[1][1] - R[2][2], 1e-12f))
              * ((R[2][1] - R[1][2] >= 0.0f) ? 1.0f : -1.0f);
    float qyv = 0.5f * sqrtf(fmaxf(1.0f - R[0][0] + R[1][1] - R[2][2], 1e-12f))
              * ((R[0][2] - R[2][0] >= 0.0f) ? 1.0f : -1.0f);
    float qzv = 0.5f * sqrtf(fmaxf(1.0f - R[0][0] - R[1][1] + R[2][2], 1e-12f))
              * ((R[1][0] - R[0][1] >= 0.0f) ? 1.0f : -1.0f);

    float* qo = out + BB * 16 + b * 4;
    qo[0] = qw; qo[1] = qxv; qo[2] = qyv; qo[3] = qzv;

    float* to = out + BB * 16 + BB * 4 + b * 3;
    to[0] = tv[0]; to[1] = tv[1]; to[2] = tv[2];
}

// ---------------------------------------------------------------------------
extern "C" void kernel_launch(void* const* d_in, const int* in_sizes, int n_in,
                              void* d_out, int out_size)
{
    const float* pc1 = (const float*)d_in[0];
    const float* pc2 = (const float*)d_in[1];
    float* out = (float*)d_out;

    dim3 g1(NN1 / 128, NSLICE, BB);
    groupmin_kernel<<<g1, 128>>>(pc1, pc2);
    dim3 g2(NN1 / 128, BB);
    resolve_kernel <<<g2, 128>>>(pc1, pc2);
    finalize_kernel<<<BB, 256>>>(pc1, out);
}